// round 4
// baseline (speedup 1.0000x reference)
#include <cuda_runtime.h>
#include <cuda_bf16.h>

// Problem constants (fixed by the reference)
#define N_USERS 100000
#define N_ITEMS 100000
#define NTOT    (N_USERS + N_ITEMS)   // 200000
#define EMBD    64
#define NNZ_E   1000000
#define NELEMS  (NTOT * EMBD)         // 12,800,000 floats

// Ping-pong propagation buffers (allocation-free scratch: __device__ globals)
__device__ float g_buf0[NELEMS];
__device__ float g_buf1[NELEMS];

// ---------------------------------------------------------------------------
// init: x0 = concat(user_w, item_w); out = x0 (acc starts at x); dst buffer = 0
// Vectorized float4 over 3.2M elements.
// ---------------------------------------------------------------------------
__global__ void k_init(const float4* __restrict__ user_w,
                       const float4* __restrict__ item_w,
                       float4* __restrict__ x0,
                       float4* __restrict__ y0,
                       float4* __restrict__ out)
{
    int i = blockIdx.x * blockDim.x + threadIdx.x;     // float4 index
    const int n4 = NELEMS / 4;
    if (i >= n4) return;
    const int user4 = (N_USERS * EMBD) / 4;
    float4 v = (i < user4) ? user_w[i] : item_w[i - user4];
    x0[i]  = v;
    out[i] = v;
    y0[i]  = make_float4(0.f, 0.f, 0.f, 0.f);
}

// ---------------------------------------------------------------------------
// SpMM (COO, edge-parallel): y[row] += val * x[col]
// 16 threads per edge; each thread handles one float4 (4 of the 64 dims).
// Gather is L2-resident (x = 51.2MB < 126MB L2); scatter uses vector float4
// atomics (sm_90+) -> 16 REDs per edge instead of 64.
// ---------------------------------------------------------------------------
__global__ void k_spmm(const float* __restrict__ vals,
                       const int*   __restrict__ rows,
                       const int*   __restrict__ cols,
                       const float* __restrict__ x,
                       float*       __restrict__ y)
{
    long long tid = (long long)blockIdx.x * blockDim.x + threadIdx.x;
    int e    = (int)(tid >> 4);        // edge index
    int part = (int)(tid & 15);        // which float4 of the 64-dim row
    if (e >= NNZ_E) return;

    int   r = __ldg(rows + e);
    int   c = __ldg(cols + e);
    float v = __ldg(vals + e);

    const float4* xr = (const float4*)(x + (long long)c * EMBD) + part;
    float4 xv = __ldg(xr);
    xv.x *= v; xv.y *= v; xv.z *= v; xv.w *= v;

    float4* yr = (float4*)(y + (long long)r * EMBD) + part;
#if __CUDA_ARCH__ >= 900
    atomicAdd(yr, xv);                 // vector RED.ADD.F32 (one 16B atomic)
#else
    float* ys = (float*)yr;
    atomicAdd(ys + 0, xv.x);
    atomicAdd(ys + 1, xv.y);
    atomicAdd(ys + 2, xv.z);
    atomicAdd(ys + 3, xv.w);
#endif
}

// ---------------------------------------------------------------------------
// consume (layers 0,1): out += y; zero the source buffer (it becomes the
// scatter target of the NEXT layer) — fuses the "zero" pass for free.
// ---------------------------------------------------------------------------
__global__ void k_consume(const float4* __restrict__ y,
                          float4*       __restrict__ src_to_zero,
                          float4*       __restrict__ out)
{
    int i = blockIdx.x * blockDim.x + threadIdx.x;
    const int n4 = NELEMS / 4;
    if (i >= n4) return;
    float4 a = out[i];
    float4 b = y[i];
    a.x += b.x; a.y += b.y; a.z += b.z; a.w += b.w;
    out[i] = a;
    src_to_zero[i] = make_float4(0.f, 0.f, 0.f, 0.f);
}

// ---------------------------------------------------------------------------
// final (layer 2): out = (out + y) / 4
// ---------------------------------------------------------------------------
__global__ void k_final(const float4* __restrict__ y,
                        float4*       __restrict__ out)
{
    int i = blockIdx.x * blockDim.x + threadIdx.x;
    const int n4 = NELEMS / 4;
    if (i >= n4) return;
    float4 a = out[i];
    float4 b = y[i];
    a.x = (a.x + b.x) * 0.25f;
    a.y = (a.y + b.y) * 0.25f;
    a.z = (a.z + b.z) * 0.25f;
    a.w = (a.w + b.w) * 0.25f;
    out[i] = a;
}

extern "C" void kernel_launch(void* const* d_in, const int* in_sizes, int n_in,
                              void* d_out, int out_size)
{
    const float* user_w = (const float*)d_in[0];
    const float* item_w = (const float*)d_in[1];
    const float* vals   = (const float*)d_in[2];
    const int*   rows   = (const int*)d_in[3];
    const int*   cols   = (const int*)d_in[4];
    float*       out    = (float*)d_out;

    float* b0;
    float* b1;
    cudaGetSymbolAddress((void**)&b0, g_buf0);
    cudaGetSymbolAddress((void**)&b1, g_buf1);

    const int n4 = NELEMS / 4;                 // 3.2M float4s
    const int TB = 256;
    const int gridElem = (n4 + TB - 1) / TB;

    // SpMM grid: NNZ * 16 threads
    const long long spmmThreads = (long long)NNZ_E * 16;
    const int gridSpmm = (int)((spmmThreads + TB - 1) / TB);

    // init: b0 = x0, out = x0, b1 = 0
    k_init<<<gridElem, TB>>>((const float4*)user_w, (const float4*)item_w,
                             (float4*)b0, (float4*)b1, (float4*)out);

    // Layer 0: y = A @ b0 -> b1 ; out += b1 ; zero b0 (next target)
    k_spmm<<<gridSpmm, TB>>>(vals, rows, cols, b0, b1);
    k_consume<<<gridElem, TB>>>((const float4*)b1, (float4*)b0, (float4*)out);

    // Layer 1: b0 = A @ b1 ; out += b0 ; zero b1 (next target)
    k_spmm<<<gridSpmm, TB>>>(vals, rows, cols, b1, b0);
    k_consume<<<gridElem, TB>>>((const float4*)b0, (float4*)b1, (float4*)out);

    // Layer 2: b1 = A @ b0 ; out = (out + b1) / 4
    k_spmm<<<gridSpmm, TB>>>(vals, rows, cols, b0, b1);
    k_final<<<gridElem, TB>>>((const float4*)b1, (float4*)out);
}

// round 5
// speedup vs baseline: 1.1242x; 1.1242x over previous
#include <cuda_runtime.h>
#include <cuda_bf16.h>

// Problem constants (fixed by the reference)
#define N_USERS 100000
#define N_ITEMS 100000
#define NTOT    (N_USERS + N_ITEMS)   // 200000
#define EMBD    64
#define NNZ_E   1000000
#define NELEMS  (NTOT * EMBD)         // 12,800,000 floats

// Three layer-output buffers (allocation-free scratch: __device__ globals).
// y1 = A@x0, y2 = A@y1, y3 = A@y2; out = (x0+y1+y2+y3)/4 in ONE pass.
__device__ float g_y1[NELEMS];
__device__ float g_y2[NELEMS];
__device__ float g_y3[NELEMS];

// ---------------------------------------------------------------------------
// zero: clear all three scatter targets (write-only, 153.6MB)
// ---------------------------------------------------------------------------
__global__ void k_zero(float4* __restrict__ a,
                       float4* __restrict__ b,
                       float4* __restrict__ c)
{
    int i = blockIdx.x * blockDim.x + threadIdx.x;
    const int n4 = NELEMS / 4;
    if (i >= n4) return;
    float4 z = make_float4(0.f, 0.f, 0.f, 0.f);
    a[i] = z; b[i] = z; c[i] = z;
}

// ---------------------------------------------------------------------------
// SpMM layer 0 (COO, edge-parallel): y[row] += val * x0[col], where x0 is the
// virtual concat(user_w, item_w) — resolved by a predicated pointer select,
// so we never materialize x0.
// 8 threads/edge, 2 float4s each -> 2 independent LDG.128 per thread (MLP=2),
// half the redundant edge-scalar loads vs 16 threads/edge.
// ---------------------------------------------------------------------------
__global__ void k_spmm_first(const float* __restrict__ vals,
                             const int*   __restrict__ rows,
                             const int*   __restrict__ cols,
                             const float* __restrict__ user_w,
                             const float* __restrict__ item_w,
                             float*       __restrict__ y)
{
    long long tid = (long long)blockIdx.x * blockDim.x + threadIdx.x;
    int e = (int)(tid >> 3);           // edge index
    int p = (int)(tid & 7);            // which pair of float4s
    if (e >= NNZ_E) return;

    int   r = __ldg(rows + e);
    int   c = __ldg(cols + e);
    float v = __ldg(vals + e);

    const float* xrow = (c < N_USERS)
        ? (user_w + (long long)c * EMBD)
        : (item_w + (long long)(c - N_USERS) * EMBD);
    const float4* xr = (const float4*)(xrow) + p * 2;
    float4 a = __ldg(xr + 0);
    float4 b = __ldg(xr + 1);
    a.x *= v; a.y *= v; a.z *= v; a.w *= v;
    b.x *= v; b.y *= v; b.z *= v; b.w *= v;

    float4* yr = (float4*)(y + (long long)r * EMBD) + p * 2;
    atomicAdd(yr + 0, a);              // vector RED.ADD.F32 (16B)
    atomicAdd(yr + 1, b);
}

// ---------------------------------------------------------------------------
// SpMM layers 1,2: y[row] += val * x[col] with materialized x.
// ---------------------------------------------------------------------------
__global__ void k_spmm(const float* __restrict__ vals,
                       const int*   __restrict__ rows,
                       const int*   __restrict__ cols,
                       const float* __restrict__ x,
                       float*       __restrict__ y)
{
    long long tid = (long long)blockIdx.x * blockDim.x + threadIdx.x;
    int e = (int)(tid >> 3);
    int p = (int)(tid & 7);
    if (e >= NNZ_E) return;

    int   r = __ldg(rows + e);
    int   c = __ldg(cols + e);
    float v = __ldg(vals + e);

    const float4* xr = (const float4*)(x + (long long)c * EMBD) + p * 2;
    float4 a = __ldg(xr + 0);
    float4 b = __ldg(xr + 1);
    a.x *= v; a.y *= v; a.z *= v; a.w *= v;
    b.x *= v; b.y *= v; b.z *= v; b.w *= v;

    float4* yr = (float4*)(y + (long long)r * EMBD) + p * 2;
    atomicAdd(yr + 0, a);
    atomicAdd(yr + 1, b);
}

// ---------------------------------------------------------------------------
// final: out = 0.25 * (x0 + y1 + y2 + y3), x0 read straight from inputs.
// Single pass: read 204.8MB, write 51.2MB.
// ---------------------------------------------------------------------------
__global__ void k_final(const float4* __restrict__ user_w,
                        const float4* __restrict__ item_w,
                        const float4* __restrict__ y1,
                        const float4* __restrict__ y2,
                        const float4* __restrict__ y3,
                        float4*       __restrict__ out)
{
    int i = blockIdx.x * blockDim.x + threadIdx.x;
    const int n4 = NELEMS / 4;
    if (i >= n4) return;
    const int user4 = (N_USERS * EMBD) / 4;
    float4 x = (i < user4) ? __ldg(user_w + i) : __ldg(item_w + (i - user4));
    float4 a = __ldg(y1 + i);
    float4 b = __ldg(y2 + i);
    float4 c = __ldg(y3 + i);
    float4 o;
    o.x = (x.x + a.x + b.x + c.x) * 0.25f;
    o.y = (x.y + a.y + b.y + c.y) * 0.25f;
    o.z = (x.z + a.z + b.z + c.z) * 0.25f;
    o.w = (x.w + a.w + b.w + c.w) * 0.25f;
    out[i] = o;
}

extern "C" void kernel_launch(void* const* d_in, const int* in_sizes, int n_in,
                              void* d_out, int out_size)
{
    const float* user_w = (const float*)d_in[0];
    const float* item_w = (const float*)d_in[1];
    const float* vals   = (const float*)d_in[2];
    const int*   rows   = (const int*)d_in[3];
    const int*   cols   = (const int*)d_in[4];
    float*       out    = (float*)d_out;

    float *y1, *y2, *y3;
    cudaGetSymbolAddress((void**)&y1, g_y1);
    cudaGetSymbolAddress((void**)&y2, g_y2);
    cudaGetSymbolAddress((void**)&y3, g_y3);

    const int n4 = NELEMS / 4;                 // 3.2M float4s
    const int TB = 256;
    const int gridElem = (n4 + TB - 1) / TB;

    // SpMM grid: NNZ * 8 threads
    const long long spmmThreads = (long long)NNZ_E * 8;
    const int gridSpmm = (int)((spmmThreads + TB - 1) / TB);

    // Clear all three scatter targets in one pass.
    k_zero<<<gridElem, TB>>>((float4*)y1, (float4*)y2, (float4*)y3);

    // y1 = A @ x0   (x0 = concat(user_w,item_w), read in place)
    k_spmm_first<<<gridSpmm, TB>>>(vals, rows, cols, user_w, item_w, y1);
    // y2 = A @ y1
    k_spmm<<<gridSpmm, TB>>>(vals, rows, cols, y1, y2);
    // y3 = A @ y2
    k_spmm<<<gridSpmm, TB>>>(vals, rows, cols, y2, y3);

    // out = (x0 + y1 + y2 + y3) / 4
    k_final<<<gridElem, TB>>>((const float4*)user_w, (const float4*)item_w,
                              (const float4*)y1, (const float4*)y2,
                              (const float4*)y3, (float4*)out);
}

// round 10
// speedup vs baseline: 1.4473x; 1.2873x over previous
#include <cuda_runtime.h>
#include <cuda_bf16.h>

// Problem constants (fixed by the reference)
#define N_USERS 100000
#define N_ITEMS 100000
#define NTOT    (N_USERS + N_ITEMS)   // 200000
#define EMBD    64
#define NNZ_E   1000000
#define NELEMS  (NTOT * EMBD)         // 12,800,000 floats

// Three layer-output buffers (allocation-free scratch: __device__ globals).
__device__ float g_y1[NELEMS];
__device__ float g_y2[NELEMS];
__device__ float g_y3[NELEMS];

// ---------------------------------------------------------------------------
// zero: clear all three scatter targets (write-only, 153.6MB)
// ---------------------------------------------------------------------------
__global__ void k_zero(float4* __restrict__ a,
                       float4* __restrict__ b,
                       float4* __restrict__ c)
{
    int i = blockIdx.x * blockDim.x + threadIdx.x;
    const int n4 = NELEMS / 4;
    if (i >= n4) return;
    float4 z = make_float4(0.f, 0.f, 0.f, 0.f);
    a[i] = z; b[i] = z; c[i] = z;
}

// ---------------------------------------------------------------------------
// SpMM (COO, edge-PAIR parallel): 16 threads per edge-pair; thread p handles
// float4 #p of BOTH edges 2g and 2g+1. The two gathers hit independent random
// rows -> true MLP=2 independent chains per thread. Edge scalars load as
// int2/int2/float2 (3 broadcast loads instead of 6).
// ---------------------------------------------------------------------------
__global__ void k_spmm(const float* __restrict__ vals,
                       const int*   __restrict__ rows,
                       const int*   __restrict__ cols,
                       const float* __restrict__ x,
                       float*       __restrict__ y)
{
    long long tid = (long long)blockIdx.x * blockDim.x + threadIdx.x;
    int g = (int)(tid >> 4);           // edge-pair index
    int p = (int)(tid & 15);           // float4 slot within the 64-dim row
    if (g >= NNZ_E / 2) return;

    int2   rr = __ldg((const int2*)rows + g);
    int2   cc = __ldg((const int2*)cols + g);
    float2 vv = __ldg((const float2*)vals + g);

    // Two independent gathers (MLP=2)
    const float4* xa = (const float4*)(x + (long long)cc.x * EMBD) + p;
    const float4* xb = (const float4*)(x + (long long)cc.y * EMBD) + p;
    float4 a = __ldg(xa);
    float4 b = __ldg(xb);
    a.x *= vv.x; a.y *= vv.x; a.z *= vv.x; a.w *= vv.x;
    b.x *= vv.y; b.y *= vv.y; b.z *= vv.y; b.w *= vv.y;

    float4* ya = (float4*)(y + (long long)rr.x * EMBD) + p;
    float4* yb = (float4*)(y + (long long)rr.y * EMBD) + p;
    atomicAdd(ya, a);                  // vector RED.ADD.F32 (16B)
    atomicAdd(yb, b);
}

// ---------------------------------------------------------------------------
// SpMM layer 0: same, but x0 is the virtual concat(user_w,item_w) resolved by
// a predicated pointer select per edge (never materialized).
// ---------------------------------------------------------------------------
__global__ void k_spmm_first(const float* __restrict__ vals,
                             const int*   __restrict__ rows,
                             const int*   __restrict__ cols,
                             const float* __restrict__ user_w,
                             const float* __restrict__ item_w,
                             float*       __restrict__ y)
{
    long long tid = (long long)blockIdx.x * blockDim.x + threadIdx.x;
    int g = (int)(tid >> 4);
    int p = (int)(tid & 15);
    if (g >= NNZ_E / 2) return;

    int2   rr = __ldg((const int2*)rows + g);
    int2   cc = __ldg((const int2*)cols + g);
    float2 vv = __ldg((const float2*)vals + g);

    const float* xrow_a = (cc.x < N_USERS)
        ? (user_w + (long long)cc.x * EMBD)
        : (item_w + (long long)(cc.x - N_USERS) * EMBD);
    const float* xrow_b = (cc.y < N_USERS)
        ? (user_w + (long long)cc.y * EMBD)
        : (item_w + (long long)(cc.y - N_USERS) * EMBD);

    float4 a = __ldg((const float4*)xrow_a + p);
    float4 b = __ldg((const float4*)xrow_b + p);
    a.x *= vv.x; a.y *= vv.x; a.z *= vv.x; a.w *= vv.x;
    b.x *= vv.y; b.y *= vv.y; b.z *= vv.y; b.w *= vv.y;

    float4* ya = (float4*)(y + (long long)rr.x * EMBD) + p;
    float4* yb = (float4*)(y + (long long)rr.y * EMBD) + p;
    atomicAdd(ya, a);
    atomicAdd(yb, b);
}

// ---------------------------------------------------------------------------
// final: out = 0.25 * (x0 + y1 + y2 + y3), x0 read straight from inputs.
// ---------------------------------------------------------------------------
__global__ void k_final(const float4* __restrict__ user_w,
                        const float4* __restrict__ item_w,
                        const float4* __restrict__ y1,
                        const float4* __restrict__ y2,
                        const float4* __restrict__ y3,
                        float4*       __restrict__ out)
{
    int i = blockIdx.x * blockDim.x + threadIdx.x;
    const int n4 = NELEMS / 4;
    if (i >= n4) return;
    const int user4 = (N_USERS * EMBD) / 4;
    float4 x = (i < user4) ? __ldg(user_w + i) : __ldg(item_w + (i - user4));
    float4 a = __ldg(y1 + i);
    float4 b = __ldg(y2 + i);
    float4 c = __ldg(y3 + i);
    float4 o;
    o.x = (x.x + a.x + b.x + c.x) * 0.25f;
    o.y = (x.y + a.y + b.y + c.y) * 0.25f;
    o.z = (x.z + a.z + b.z + c.z) * 0.25f;
    o.w = (x.w + a.w + b.w + c.w) * 0.25f;
    out[i] = o;
}

extern "C" void kernel_launch(void* const* d_in, const int* in_sizes, int n_in,
                              void* d_out, int out_size)
{
    const float* user_w = (const float*)d_in[0];
    const float* item_w = (const float*)d_in[1];
    const float* vals   = (const float*)d_in[2];
    const int*   rows   = (const int*)d_in[3];
    const int*   cols   = (const int*)d_in[4];
    float*       out    = (float*)d_out;

    float *y1, *y2, *y3;
    cudaGetSymbolAddress((void**)&y1, g_y1);
    cudaGetSymbolAddress((void**)&y2, g_y2);
    cudaGetSymbolAddress((void**)&y3, g_y3);

    const int n4 = NELEMS / 4;                 // 3.2M float4s
    const int TB = 256;
    const int gridElem = (n4 + TB - 1) / TB;

    // SpMM grid: (NNZ/2) edge-pairs * 16 threads
    const long long spmmThreads = (long long)(NNZ_E / 2) * 16;
    const int gridSpmm = (int)((spmmThreads + TB - 1) / TB);

    // Clear all three scatter targets in one pass.
    k_zero<<<gridElem, TB>>>((float4*)y1, (float4*)y2, (float4*)y3);

    // y1 = A @ x0   (x0 = concat(user_w,item_w), read in place)
    k_spmm_first<<<gridSpmm, TB>>>(vals, rows, cols, user_w, item_w, y1);
    // y2 = A @ y1
    k_spmm<<<gridSpmm, TB>>>(vals, rows, cols, y1, y2);
    // y3 = A @ y2
    k_spmm<<<gridSpmm, TB>>>(vals, rows, cols, y2, y3);

    // out = (x0 + y1 + y2 + y3) / 4
    k_final<<<gridElem, TB>>>((const float4*)user_w, (const float4*)item_w,
                              (const float4*)y1, (const float4*)y2,
                              (const float4*)y3, (float4*)out);
}

// round 11
// speedup vs baseline: 1.6783x; 1.1597x over previous
#include <cuda_runtime.h>
#include <cuda_bf16.h>

// Problem constants (fixed by the reference)
#define N_USERS 100000
#define N_ITEMS 100000
#define NTOT    (N_USERS + N_ITEMS)   // 200000
#define EMBD    64
#define NNZ_E   1000000
#define NELEMS  (NTOT * EMBD)         // 12,800,000 floats

// Layer-output buffers (allocation-free scratch: __device__ globals).
// y3 is never materialized: layer 3 scatters 0.25*v*y2[col] straight into out.
__device__ float g_y1[NELEMS];
__device__ float g_y2[NELEMS];

// ---------------------------------------------------------------------------
// zero: clear the two scatter targets (write-only, 102.4MB)
// ---------------------------------------------------------------------------
__global__ void k_zero(float4* __restrict__ a,
                       float4* __restrict__ b)
{
    int i = blockIdx.x * blockDim.x + threadIdx.x;
    const int n4 = NELEMS / 4;
    if (i >= n4) return;
    float4 z = make_float4(0.f, 0.f, 0.f, 0.f);
    a[i] = z; b[i] = z;
}

__device__ __forceinline__ float4 scale4(float4 a, float v)
{
    a.x *= v; a.y *= v; a.z *= v; a.w *= v;
    return a;
}

// ---------------------------------------------------------------------------
// SpMM (COO, edge-QUAD parallel): 16 threads per 4 edges; thread p handles
// float4 slot #p of edges 4g..4g+3. Four independent random-row gathers per
// thread (MLP=4) + four vector REDs. Edge scalars: 3 broadcast 16B loads.
// 'scale' folds the final /4 into layer 3 (scale=0.25, target=d_out).
// ---------------------------------------------------------------------------
__global__ void k_spmm(const float4* __restrict__ vals4,
                       const int4*   __restrict__ rows4,
                       const int4*   __restrict__ cols4,
                       const float*  __restrict__ x,
                       float*        __restrict__ y,
                       float scale)
{
    long long tid = (long long)blockIdx.x * blockDim.x + threadIdx.x;
    int g = (int)(tid >> 4);           // edge-quad index
    int p = (int)(tid & 15);           // float4 slot within the 64-dim row
    if (g >= NNZ_E / 4) return;

    int4   rr = __ldg(rows4 + g);
    int4   cc = __ldg(cols4 + g);
    float4 vv = __ldg(vals4 + g);

    // Four independent gathers (MLP=4)
    float4 a = __ldg((const float4*)(x + (long long)cc.x * EMBD) + p);
    float4 b = __ldg((const float4*)(x + (long long)cc.y * EMBD) + p);
    float4 c = __ldg((const float4*)(x + (long long)cc.z * EMBD) + p);
    float4 d = __ldg((const float4*)(x + (long long)cc.w * EMBD) + p);
    a = scale4(a, vv.x * scale);
    b = scale4(b, vv.y * scale);
    c = scale4(c, vv.z * scale);
    d = scale4(d, vv.w * scale);

    atomicAdd((float4*)(y + (long long)rr.x * EMBD) + p, a);
    atomicAdd((float4*)(y + (long long)rr.y * EMBD) + p, b);
    atomicAdd((float4*)(y + (long long)rr.z * EMBD) + p, c);
    atomicAdd((float4*)(y + (long long)rr.w * EMBD) + p, d);
}

// ---------------------------------------------------------------------------
// SpMM layer 0: x0 is the virtual concat(user_w,item_w), resolved per-edge by
// a predicated pointer select (never materialized).
// ---------------------------------------------------------------------------
__global__ void k_spmm_first(const float4* __restrict__ vals4,
                             const int4*   __restrict__ rows4,
                             const int4*   __restrict__ cols4,
                             const float*  __restrict__ user_w,
                             const float*  __restrict__ item_w,
                             float*        __restrict__ y)
{
    long long tid = (long long)blockIdx.x * blockDim.x + threadIdx.x;
    int g = (int)(tid >> 4);
    int p = (int)(tid & 15);
    if (g >= NNZ_E / 4) return;

    int4   rr = __ldg(rows4 + g);
    int4   cc = __ldg(cols4 + g);
    float4 vv = __ldg(vals4 + g);

    const float* xa = (cc.x < N_USERS) ? (user_w + (long long)cc.x * EMBD)
                                       : (item_w + (long long)(cc.x - N_USERS) * EMBD);
    const float* xb = (cc.y < N_USERS) ? (user_w + (long long)cc.y * EMBD)
                                       : (item_w + (long long)(cc.y - N_USERS) * EMBD);
    const float* xc = (cc.z < N_USERS) ? (user_w + (long long)cc.z * EMBD)
                                       : (item_w + (long long)(cc.z - N_USERS) * EMBD);
    const float* xd = (cc.w < N_USERS) ? (user_w + (long long)cc.w * EMBD)
                                       : (item_w + (long long)(cc.w - N_USERS) * EMBD);

    float4 a = __ldg((const float4*)xa + p);
    float4 b = __ldg((const float4*)xb + p);
    float4 c = __ldg((const float4*)xc + p);
    float4 d = __ldg((const float4*)xd + p);
    a = scale4(a, vv.x);
    b = scale4(b, vv.y);
    c = scale4(c, vv.z);
    d = scale4(d, vv.w);

    atomicAdd((float4*)(y + (long long)rr.x * EMBD) + p, a);
    atomicAdd((float4*)(y + (long long)rr.y * EMBD) + p, b);
    atomicAdd((float4*)(y + (long long)rr.z * EMBD) + p, c);
    atomicAdd((float4*)(y + (long long)rr.w * EMBD) + p, d);
}

// ---------------------------------------------------------------------------
// prefinal: out = 0.25 * (x0 + y1 + y2). Layer 3 then atomically adds
// 0.25*v*y2[col] into out, completing out = (x0+y1+y2+y3)/4.
// ---------------------------------------------------------------------------
__global__ void k_prefinal(const float4* __restrict__ user_w,
                           const float4* __restrict__ item_w,
                           const float4* __restrict__ y1,
                           const float4* __restrict__ y2,
                           float4*       __restrict__ out)
{
    int i = blockIdx.x * blockDim.x + threadIdx.x;
    const int n4 = NELEMS / 4;
    if (i >= n4) return;
    const int user4 = (N_USERS * EMBD) / 4;
    float4 x = (i < user4) ? __ldg(user_w + i) : __ldg(item_w + (i - user4));
    float4 a = __ldg(y1 + i);
    float4 b = __ldg(y2 + i);
    float4 o;
    o.x = (x.x + a.x + b.x) * 0.25f;
    o.y = (x.y + a.y + b.y) * 0.25f;
    o.z = (x.z + a.z + b.z) * 0.25f;
    o.w = (x.w + a.w + b.w) * 0.25f;
    out[i] = o;
}

extern "C" void kernel_launch(void* const* d_in, const int* in_sizes, int n_in,
                              void* d_out, int out_size)
{
    const float* user_w = (const float*)d_in[0];
    const float* item_w = (const float*)d_in[1];
    const float* vals   = (const float*)d_in[2];
    const int*   rows   = (const int*)d_in[3];
    const int*   cols   = (const int*)d_in[4];
    float*       out    = (float*)d_out;

    float *y1, *y2;
    cudaGetSymbolAddress((void**)&y1, g_y1);
    cudaGetSymbolAddress((void**)&y2, g_y2);

    const int n4 = NELEMS / 4;                 // 3.2M float4s
    const int TB = 256;
    const int gridElem = (n4 + TB - 1) / TB;

    // SpMM grid: (NNZ/4) edge-quads * 16 threads
    const long long spmmThreads = (long long)(NNZ_E / 4) * 16;
    const int gridSpmm = (int)((spmmThreads + TB - 1) / TB);

    // Clear the two materialized scatter targets.
    k_zero<<<gridElem, TB>>>((float4*)y1, (float4*)y2);

    // y1 = A @ x0   (x0 = concat(user_w,item_w), read in place)
    k_spmm_first<<<gridSpmm, TB>>>((const float4*)vals, (const int4*)rows,
                                   (const int4*)cols, user_w, item_w, y1);
    // y2 = A @ y1
    k_spmm<<<gridSpmm, TB>>>((const float4*)vals, (const int4*)rows,
                             (const int4*)cols, y1, y2, 1.0f);

    // out = 0.25*(x0 + y1 + y2)
    k_prefinal<<<gridElem, TB>>>((const float4*)user_w, (const float4*)item_w,
                                 (const float4*)y1, (const float4*)y2,
                                 (float4*)out);

    // out += 0.25 * (A @ y2)   (y3 never materialized)
    k_spmm<<<gridSpmm, TB>>>((const float4*)vals, (const int4*)rows,
                             (const int4*)cols, y2, out, 0.25f);
}